// round 1
// baseline (speedup 1.0000x reference)
#include <cuda_runtime.h>
#include <cuda_bf16.h>
#include <math.h>

// ---------------------------------------------------------------------------
// RWKV6 ChannelMix, shape-specialized:
//   B=4, T=2048, C=4096, F=14336, M=B*T=8192
//   out  = sigmoid(xr @ Rw^T) * ( relu(xk @ Kw^T)^2 @ Vw^T )
//   new_state = x[:, -1, :]
// All three GEMMs are TN (K contiguous in both operands).
// ---------------------------------------------------------------------------

#define BDIM 4
#define TDIM 2048
#define CDIM 4096
#define FDIM 14336
#define MDIM (BDIM * TDIM)   // 8192

// Scratch (device globals: allocation-free rule)
__device__ float g_xk[(size_t)MDIM * CDIM];           // 134 MB
__device__ float g_xr[(size_t)MDIM * CDIM];           // 134 MB
__device__ float g_s [(size_t)MDIM * FDIM];           // 470 MB  relu(k)^2
__device__ float g_r [(size_t)MDIM * CDIM];           // 134 MB  sigmoid(...)

// ---------------------------------------------------------------------------
// packed f32x2 helpers (FFMA2 path on sm_103a)
// ---------------------------------------------------------------------------
__device__ __forceinline__ unsigned long long pk2(float x, float y) {
    unsigned long long r;
    asm("mov.b64 %0, {%1, %2};" : "=l"(r) : "f"(x), "f"(y));
    return r;
}
__device__ __forceinline__ unsigned long long dup2(float x) {
    unsigned long long r;
    asm("mov.b64 %0, {%1, %1};" : "=l"(r) : "f"(x));
    return r;
}
__device__ __forceinline__ void upk2(unsigned long long v, float& x, float& y) {
    asm("mov.b64 {%0, %1}, %2;" : "=f"(x), "=f"(y) : "l"(v));
}
__device__ __forceinline__ void fma2(unsigned long long& c,
                                     unsigned long long a,
                                     unsigned long long b) {
    asm("fma.rn.f32x2 %0, %1, %2, %0;" : "+l"(c) : "l"(a), "l"(b));
}

// ---------------------------------------------------------------------------
// Elementwise token-shift mix: xk/xr = x + (shift(x) - x) * maa
// vectorized float4, C divisible by 4
// ---------------------------------------------------------------------------
__global__ void mix_kernel(const float4* __restrict__ x,
                           const float4* __restrict__ ls,
                           const float4* __restrict__ mk,
                           const float4* __restrict__ mr,
                           float4* __restrict__ xk,
                           float4* __restrict__ xr) {
    const int C4 = CDIM / 4;
    int idx = blockIdx.x * blockDim.x + threadIdx.x;   // < MDIM*C4 = 8,388,608
    int c4 = idx % C4;
    int bt = idx / C4;
    int t  = bt % TDIM;
    int b  = bt / TDIM;

    float4 xv = x[idx];
    float4 pv = (t == 0) ? ls[b * C4 + c4] : x[idx - C4];
    float4 k4 = mk[c4];
    float4 r4 = mr[c4];

    float4 ok, orr;
    ok.x  = fmaf(pv.x - xv.x, k4.x, xv.x);
    ok.y  = fmaf(pv.y - xv.y, k4.y, xv.y);
    ok.z  = fmaf(pv.z - xv.z, k4.z, xv.z);
    ok.w  = fmaf(pv.w - xv.w, k4.w, xv.w);
    orr.x = fmaf(pv.x - xv.x, r4.x, xv.x);
    orr.y = fmaf(pv.y - xv.y, r4.y, xv.y);
    orr.z = fmaf(pv.z - xv.z, r4.z, xv.z);
    orr.w = fmaf(pv.w - xv.w, r4.w, xv.w);
    xk[idx] = ok;
    xr[idx] = orr;
}

// ---------------------------------------------------------------------------
// new_state = x[:, T-1, :]
// ---------------------------------------------------------------------------
__global__ void state_kernel(const float* __restrict__ x, float* __restrict__ outs) {
    int idx = blockIdx.x * blockDim.x + threadIdx.x;   // < B*C = 16384
    int b = idx / CDIM;
    int c = idx % CDIM;
    outs[idx] = x[((size_t)b * TDIM + (TDIM - 1)) * CDIM + c];
}

// ---------------------------------------------------------------------------
// TN GEMM: C[M,N] = A[M,K] * B[N,K]^T, with fused epilogue
//   epi 0: relu(v)^2
//   epi 1: sigmoid(v)
//   epi 2: v * Rm[row*N+col]
// Tiles: 128x128x16, 256 threads, 8x8 per-thread, f32x2 packed FMAs,
// double-buffered shared memory (transposed tiles with +4 padding).
// ---------------------------------------------------------------------------
#define BM 128
#define BN 128
#define BK 16
#define SPAD 4

__global__ __launch_bounds__(256, 2)
void gemm_tn(const float* __restrict__ A, const float* __restrict__ B,
             float* __restrict__ Cout, const float* __restrict__ Rm,
             int N, int K, int epi) {
    __shared__ float As[2][BK][BM + SPAD];
    __shared__ float Bs[2][BK][BN + SPAD];

    const int tid  = threadIdx.x;
    const int lrow = tid >> 2;        // 0..63
    const int lcol = tid & 3;         // 0..3  (16B chunk within 64B k-slice)
    const int tx   = tid & 15;
    const int ty   = tid >> 4;

    const float* Ab = A + (size_t)blockIdx.y * BM * K;
    const float* Bb = B + (size_t)blockIdx.x * BN * K;

    float4 ra[2], rb[2];

    // prologue: load k-tile 0
#pragma unroll
    for (int p = 0; p < 2; ++p) {
        ra[p] = *reinterpret_cast<const float4*>(Ab + (size_t)(lrow + 64 * p) * K + lcol * 4);
        rb[p] = *reinterpret_cast<const float4*>(Bb + (size_t)(lrow + 64 * p) * K + lcol * 4);
    }
#pragma unroll
    for (int p = 0; p < 2; ++p) {
        int r = lrow + 64 * p;
        As[0][lcol * 4 + 0][r] = ra[p].x;
        As[0][lcol * 4 + 1][r] = ra[p].y;
        As[0][lcol * 4 + 2][r] = ra[p].z;
        As[0][lcol * 4 + 3][r] = ra[p].w;
        Bs[0][lcol * 4 + 0][r] = rb[p].x;
        Bs[0][lcol * 4 + 1][r] = rb[p].y;
        Bs[0][lcol * 4 + 2][r] = rb[p].z;
        Bs[0][lcol * 4 + 3][r] = rb[p].w;
    }
    __syncthreads();

    unsigned long long acc[8][4];
#pragma unroll
    for (int i = 0; i < 8; ++i)
#pragma unroll
        for (int j = 0; j < 4; ++j) acc[i][j] = 0ULL;

    const int nk = K / BK;
    int buf = 0;
    for (int kt = 0; kt < nk; ++kt) {
        // prefetch next tile from global
        if (kt + 1 < nk) {
            int ko = (kt + 1) * BK;
#pragma unroll
            for (int p = 0; p < 2; ++p) {
                ra[p] = *reinterpret_cast<const float4*>(Ab + (size_t)(lrow + 64 * p) * K + ko + lcol * 4);
                rb[p] = *reinterpret_cast<const float4*>(Bb + (size_t)(lrow + 64 * p) * K + ko + lcol * 4);
            }
        }

        // compute on current buffer
#pragma unroll
        for (int k = 0; k < BK; ++k) {
            const float4 a0 = *reinterpret_cast<const float4*>(&As[buf][k][ty * 8]);
            const float4 a1 = *reinterpret_cast<const float4*>(&As[buf][k][ty * 8 + 4]);
            const float4 b0 = *reinterpret_cast<const float4*>(&Bs[buf][k][tx * 8]);
            const float4 b1 = *reinterpret_cast<const float4*>(&Bs[buf][k][tx * 8 + 4]);
            unsigned long long bb0 = pk2(b0.x, b0.y);
            unsigned long long bb1 = pk2(b0.z, b0.w);
            unsigned long long bb2 = pk2(b1.x, b1.y);
            unsigned long long bb3 = pk2(b1.z, b1.w);
            const float av[8] = {a0.x, a0.y, a0.z, a0.w, a1.x, a1.y, a1.z, a1.w};
#pragma unroll
            for (int i = 0; i < 8; ++i) {
                unsigned long long ad = dup2(av[i]);
                fma2(acc[i][0], ad, bb0);
                fma2(acc[i][1], ad, bb1);
                fma2(acc[i][2], ad, bb2);
                fma2(acc[i][3], ad, bb3);
            }
        }

        // stage next tile into the other buffer
        if (kt + 1 < nk) {
            int nbuf = buf ^ 1;
#pragma unroll
            for (int p = 0; p < 2; ++p) {
                int r = lrow + 64 * p;
                As[nbuf][lcol * 4 + 0][r] = ra[p].x;
                As[nbuf][lcol * 4 + 1][r] = ra[p].y;
                As[nbuf][lcol * 4 + 2][r] = ra[p].z;
                As[nbuf][lcol * 4 + 3][r] = ra[p].w;
                Bs[nbuf][lcol * 4 + 0][r] = rb[p].x;
                Bs[nbuf][lcol * 4 + 1][r] = rb[p].y;
                Bs[nbuf][lcol * 4 + 2][r] = rb[p].z;
                Bs[nbuf][lcol * 4 + 3][r] = rb[p].w;
            }
            __syncthreads();
            buf = nbuf;
        }
    }

    // epilogue
    const size_t row0 = (size_t)blockIdx.y * BM + ty * 8;
    const size_t col0 = (size_t)blockIdx.x * BN + tx * 8;
#pragma unroll
    for (int i = 0; i < 8; ++i) {
        const size_t base = (row0 + i) * (size_t)N + col0;
#pragma unroll
        for (int jp = 0; jp < 4; ++jp) {
            float lo, hi;
            upk2(acc[i][jp], lo, hi);
            if (epi == 0) {                 // relu^2
                lo = fmaxf(lo, 0.0f); lo = lo * lo;
                hi = fmaxf(hi, 0.0f); hi = hi * hi;
            } else if (epi == 1) {          // sigmoid
                lo = 1.0f / (1.0f + expf(-lo));
                hi = 1.0f / (1.0f + expf(-hi));
            } else {                        // * r
                const float2 rv = *reinterpret_cast<const float2*>(Rm + base + jp * 2);
                lo *= rv.x;
                hi *= rv.y;
            }
            float2 o; o.x = lo; o.y = hi;
            *reinterpret_cast<float2*>(Cout + base + jp * 2) = o;
        }
    }
}

// ---------------------------------------------------------------------------
// launch
// ---------------------------------------------------------------------------
extern "C" void kernel_launch(void* const* d_in, const int* in_sizes, int n_in,
                              void* d_out, int out_size) {
    const float* x  = (const float*)d_in[0];
    const float* ls = (const float*)d_in[1];
    const float* mk = (const float*)d_in[2];
    const float* mr = (const float*)d_in[3];
    const float* kw = (const float*)d_in[4];   // (F, C)
    const float* rw = (const float*)d_in[5];   // (C, C)
    const float* vw = (const float*)d_in[6];   // (C, F)
    float* out = (float*)d_out;

    float *xk, *xr, *s, *r;
    cudaGetSymbolAddress((void**)&xk, g_xk);
    cudaGetSymbolAddress((void**)&xr, g_xr);
    cudaGetSymbolAddress((void**)&s,  g_s);
    cudaGetSymbolAddress((void**)&r,  g_r);

    // 1) token-shift mix
    {
        int total = MDIM * (CDIM / 4);
        mix_kernel<<<total / 256, 256>>>((const float4*)x, (const float4*)ls,
                                         (const float4*)mk, (const float4*)mr,
                                         (float4*)xk, (float4*)xr);
    }

    // 2) S = relu(xk @ Kw^T)^2            [M=8192, N=14336, K=4096]
    gemm_tn<<<dim3(FDIM / BN, MDIM / BM), 256>>>(xk, kw, s, nullptr, FDIM, CDIM, 0);

    // 3) R = sigmoid(xr @ Rw^T)           [M=8192, N=4096, K=4096]
    gemm_tn<<<dim3(CDIM / BN, MDIM / BM), 256>>>(xr, rw, r, nullptr, CDIM, CDIM, 1);

    // 4) out = R * (S @ Vw^T)             [M=8192, N=4096, K=14336]
    gemm_tn<<<dim3(CDIM / BN, MDIM / BM), 256>>>(s, vw, out, r, CDIM, FDIM, 2);

    // 5) new_state = x[:, -1, :]
    state_kernel<<<(BDIM * CDIM) / 256, 256>>>(x, out + (size_t)MDIM * CDIM);
}

// round 3
// speedup vs baseline: 2.2901x; 2.2901x over previous
#include <cuda_runtime.h>
#include <cuda_bf16.h>
#include <cstdint>
#include <math.h>

#define BDIM 4
#define TDIM 2048
#define CDIM 4096
#define FDIM 14336
#define MDIM (BDIM * TDIM)   // 8192

// ---------------- scratch (device globals; allocation-free rule) -----------
__device__ __nv_bfloat16 g_xkh[(size_t)MDIM * CDIM];
__device__ __nv_bfloat16 g_xkl[(size_t)MDIM * CDIM];
__device__ __nv_bfloat16 g_xrh[(size_t)MDIM * CDIM];
__device__ __nv_bfloat16 g_xrl[(size_t)MDIM * CDIM];
__device__ __nv_bfloat16 g_sh [(size_t)MDIM * FDIM];
__device__ __nv_bfloat16 g_sl [(size_t)MDIM * FDIM];
__device__ __nv_bfloat16 g_kwh[(size_t)FDIM * CDIM];
__device__ __nv_bfloat16 g_kwl[(size_t)FDIM * CDIM];
__device__ __nv_bfloat16 g_rwh[(size_t)CDIM * CDIM];
__device__ __nv_bfloat16 g_rwl[(size_t)CDIM * CDIM];
__device__ __nv_bfloat16 g_vwh[(size_t)CDIM * FDIM];
__device__ __nv_bfloat16 g_vwl[(size_t)CDIM * FDIM];
__device__ float         g_r  [(size_t)MDIM * CDIM];

// ---------------- helpers ----------------------------------------------------
__device__ __forceinline__ uint32_t smem_u32(const void* p) {
    uint32_t a;
    asm("{ .reg .u64 t; cvta.to.shared.u64 t, %1; cvt.u32.u64 %0, t; }" : "=r"(a) : "l"(p));
    return a;
}
__device__ __forceinline__ void cpa16(uint32_t dst, const void* src) {
    asm volatile("cp.async.cg.shared.global [%0], [%1], 16;" :: "r"(dst), "l"(src));
}
__device__ __forceinline__ void ldsm4(uint32_t& r0, uint32_t& r1, uint32_t& r2, uint32_t& r3,
                                      uint32_t addr) {
    asm volatile("ldmatrix.sync.aligned.m8n8.x4.shared.b16 {%0,%1,%2,%3}, [%4];"
                 : "=r"(r0), "=r"(r1), "=r"(r2), "=r"(r3) : "r"(addr));
}
__device__ __forceinline__ void mma_bf16(float* c, const uint32_t* a, const uint32_t* b) {
    asm volatile(
        "mma.sync.aligned.m16n8k16.row.col.f32.bf16.bf16.f32 "
        "{%0,%1,%2,%3}, {%4,%5,%6,%7}, {%8,%9}, {%0,%1,%2,%3};"
        : "+f"(c[0]), "+f"(c[1]), "+f"(c[2]), "+f"(c[3])
        : "r"(a[0]), "r"(a[1]), "r"(a[2]), "r"(a[3]), "r"(b[0]), "r"(b[1]));
}
__device__ __forceinline__ uint32_t pbf2(__nv_bfloat16 a, __nv_bfloat16 b) {
    __nv_bfloat162 t = __halves2bfloat162(a, b);
    return *reinterpret_cast<uint32_t*>(&t);
}
__device__ __forceinline__ void split1(float v, __nv_bfloat16& h, __nv_bfloat16& l) {
    h = __float2bfloat16_rn(v);
    l = __float2bfloat16_rn(v - __bfloat162float(h));
}

// ---------------- elementwise kernels ---------------------------------------
__global__ void mix_split_kernel(const float4* __restrict__ x,
                                 const float4* __restrict__ ls,
                                 const float4* __restrict__ mk,
                                 const float4* __restrict__ mr,
                                 uint2* __restrict__ xkh, uint2* __restrict__ xkl,
                                 uint2* __restrict__ xrh, uint2* __restrict__ xrl) {
    const int C4 = CDIM / 4;
    int idx = blockIdx.x * blockDim.x + threadIdx.x;
    int c4 = idx % C4;
    int bt = idx / C4;
    int t  = bt % TDIM;
    int b  = bt / TDIM;

    float4 xv = x[idx];
    float4 pv = (t == 0) ? ls[b * C4 + c4] : x[idx - C4];
    float4 k4 = mk[c4];
    float4 r4 = mr[c4];

    float kk[4], rr[4];
    kk[0] = fmaf(pv.x - xv.x, k4.x, xv.x);
    kk[1] = fmaf(pv.y - xv.y, k4.y, xv.y);
    kk[2] = fmaf(pv.z - xv.z, k4.z, xv.z);
    kk[3] = fmaf(pv.w - xv.w, k4.w, xv.w);
    rr[0] = fmaf(pv.x - xv.x, r4.x, xv.x);
    rr[1] = fmaf(pv.y - xv.y, r4.y, xv.y);
    rr[2] = fmaf(pv.z - xv.z, r4.z, xv.z);
    rr[3] = fmaf(pv.w - xv.w, r4.w, xv.w);

    __nv_bfloat16 h0, l0, h1, l1, h2, l2, h3, l3;
    split1(kk[0], h0, l0); split1(kk[1], h1, l1);
    split1(kk[2], h2, l2); split1(kk[3], h3, l3);
    xkh[idx] = make_uint2(pbf2(h0, h1), pbf2(h2, h3));
    xkl[idx] = make_uint2(pbf2(l0, l1), pbf2(l2, l3));
    split1(rr[0], h0, l0); split1(rr[1], h1, l1);
    split1(rr[2], h2, l2); split1(rr[3], h3, l3);
    xrh[idx] = make_uint2(pbf2(h0, h1), pbf2(h2, h3));
    xrl[idx] = make_uint2(pbf2(l0, l1), pbf2(l2, l3));
}

__global__ void split_kernel(const float4* __restrict__ in,
                             uint4* __restrict__ oh, uint4* __restrict__ ol,
                             size_t n8) {
    size_t i = (size_t)blockIdx.x * blockDim.x + threadIdx.x;
    if (i >= n8) return;
    float4 a = in[2 * i], b = in[2 * i + 1];
    float v[8] = {a.x, a.y, a.z, a.w, b.x, b.y, b.z, b.w};
    uint32_t hw[4], lw[4];
#pragma unroll
    for (int j = 0; j < 4; ++j) {
        __nv_bfloat16 h0, l0, h1, l1;
        split1(v[2 * j], h0, l0);
        split1(v[2 * j + 1], h1, l1);
        hw[j] = pbf2(h0, h1);
        lw[j] = pbf2(l0, l1);
    }
    oh[i] = make_uint4(hw[0], hw[1], hw[2], hw[3]);
    ol[i] = make_uint4(lw[0], lw[1], lw[2], lw[3]);
}

__global__ void state_kernel(const float* __restrict__ x, float* __restrict__ outs) {
    int idx = blockIdx.x * blockDim.x + threadIdx.x;
    int b = idx / CDIM;
    int c = idx % CDIM;
    outs[idx] = x[((size_t)b * TDIM + (TDIM - 1)) * CDIM + c];
}

// ---------------- HMMA GEMM --------------------------------------------------
// C[M,N] = A[M,K]*B[N,K]^T, split bf16 3-term, mma.sync m16n8k16 bf16.
// CTA 128x128, BK=32, 3-stage cp.async, 8 warps (warp tile 64x32).
// smem stage layout: Ah | Al | Bh | Bl, each 128 rows x 80B (64B data + 16B pad)
#define ROWB   80
#define SECT   (128 * ROWB)          // 10240
#define STAGEB (4 * SECT)            // 40960
#define NSTAGE 3
#define SMEMSZ (NSTAGE * STAGEB)     // 122880

__global__ void __launch_bounds__(256, 1)
gemm_mma(const __nv_bfloat16* __restrict__ Ah, const __nv_bfloat16* __restrict__ Al,
         const __nv_bfloat16* __restrict__ Bh, const __nv_bfloat16* __restrict__ Bl,
         int N, int K, int Ntiles, int epi,
         float* __restrict__ Cf,
         __nv_bfloat16* __restrict__ Ch, __nv_bfloat16* __restrict__ Cl,
         const float* __restrict__ Rm) {
    extern __shared__ char smem[];
    const uint32_t sb = smem_u32(smem);
    const int tid  = threadIdx.x;
    const int wid  = tid >> 5;
    const int lane = tid & 31;
    const int wm   = wid & 1;        // 2 warp-rows (64 each)
    const int wn   = wid >> 1;       // 4 warp-cols (32 each)

    // band-swizzled tile mapping (bands of 16 M-tiles)
    int bid = blockIdx.x;
    int bandCtas = 16 * Ntiles;
    int band = bid / bandCtas, rmd = bid % bandCtas;
    int nt = rmd >> 4;
    int mt = band * 16 + (rmd & 15);
    const size_t m0 = (size_t)mt * 128;
    const size_t n0 = (size_t)nt * 128;

    const size_t K2 = (size_t)K * 2;  // bytes per row
    const char* pAh = (const char*)(Ah + m0 * (size_t)K);
    const char* pAl = (const char*)(Al + m0 * (size_t)K);
    const char* pBh = (const char*)(Bh + n0 * (size_t)K);
    const char* pBl = (const char*)(Bl + n0 * (size_t)K);

    const int nk = K >> 5;   // BK = 32

    // per-thread load coords: 512 16B-chunks per section, 2 per thread
    const int r0c = tid >> 2, c0c = tid & 3;             // chunk 0
    const int r1c = (tid + 256) >> 2, c1c = tid & 3;     // chunk 1

    // prologue: stages 0, 1
#pragma unroll
    for (int s = 0; s < 2; ++s) {
        const uint32_t base = sb + s * STAGEB;
        const size_t kb = (size_t)s * 64;
        {
            uint32_t off = (uint32_t)(r0c * ROWB + c0c * 16);
            size_t g = (size_t)r0c * K2 + kb + (size_t)c0c * 16;
            cpa16(base + off,            pAh + g);
            cpa16(base + SECT + off,     pAl + g);
            cpa16(base + 2 * SECT + off, pBh + g);
            cpa16(base + 3 * SECT + off, pBl + g);
        }
        {
            uint32_t off = (uint32_t)(r1c * ROWB + c1c * 16);
            size_t g = (size_t)r1c * K2 + kb + (size_t)c1c * 16;
            cpa16(base + off,            pAh + g);
            cpa16(base + SECT + off,     pAl + g);
            cpa16(base + 2 * SECT + off, pBh + g);
            cpa16(base + 3 * SECT + off, pBl + g);
        }
        asm volatile("cp.async.commit_group;" ::: "memory");
    }

    float acc[4][4][4];
#pragma unroll
    for (int i = 0; i < 4; ++i)
#pragma unroll
        for (int j = 0; j < 4; ++j)
#pragma unroll
            for (int q = 0; q < 4; ++q) acc[i][j][q] = 0.0f;

    // ldmatrix lane offsets
    const uint32_t a_lo = (uint32_t)(((lane & 7) + ((lane >> 3) & 1) * 8) * ROWB + (lane >> 4) * 16);
    const uint32_t b_lo = (uint32_t)(((lane & 7) + (lane >> 4) * 8) * ROWB + ((lane >> 3) & 1) * 16);

    for (int kt = 0; kt < nk; ++kt) {
        asm volatile("cp.async.wait_group 1;" ::: "memory");
        __syncthreads();

        const uint32_t sbase = sb + (kt % NSTAGE) * STAGEB;
        const uint32_t aBh = sbase;
        const uint32_t aBl2 = sbase + SECT;
        const uint32_t bBh = sbase + 2 * SECT;
        const uint32_t bBl2 = sbase + 3 * SECT;

#pragma unroll
        for (int kk = 0; kk < 2; ++kk) {
            const uint32_t kbyte = kk * 32;
            uint32_t ah[4][4], al[4][4], bh[4][2], bl[4][2];
#pragma unroll
            for (int mi = 0; mi < 4; ++mi) {
                uint32_t ra = (uint32_t)((wm * 64 + mi * 16) * ROWB) + kbyte + a_lo;
                ldsm4(ah[mi][0], ah[mi][1], ah[mi][2], ah[mi][3], aBh + ra);
                ldsm4(al[mi][0], al[mi][1], al[mi][2], al[mi][3], aBl2 + ra);
            }
#pragma unroll
            for (int nj = 0; nj < 2; ++nj) {
                uint32_t rb = (uint32_t)((wn * 32 + nj * 16) * ROWB) + kbyte + b_lo;
                uint32_t t0, t1, t2, t3;
                ldsm4(t0, t1, t2, t3, bBh + rb);
                bh[nj * 2][0] = t0; bh[nj * 2][1] = t1;
                bh[nj * 2 + 1][0] = t2; bh[nj * 2 + 1][1] = t3;
                ldsm4(t0, t1, t2, t3, bBl2 + rb);
                bl[nj * 2][0] = t0; bl[nj * 2][1] = t1;
                bl[nj * 2 + 1][0] = t2; bl[nj * 2 + 1][1] = t3;
            }
#pragma unroll
            for (int mi = 0; mi < 4; ++mi)
#pragma unroll
                for (int ni = 0; ni < 4; ++ni) {
                    mma_bf16(acc[mi][ni], ah[mi], bh[ni]);
                    mma_bf16(acc[mi][ni], ah[mi], bl[ni]);
                    mma_bf16(acc[mi][ni], al[mi], bh[ni]);
                }
        }

        // stage kt+2 loads (always commit one group)
        if (kt + 2 < nk) {
            const uint32_t base = sb + ((kt + 2) % NSTAGE) * STAGEB;
            const size_t kb = (size_t)(kt + 2) * 64;
            {
                uint32_t off = (uint32_t)(r0c * ROWB + c0c * 16);
                size_t g = (size_t)r0c * K2 + kb + (size_t)c0c * 16;
                cpa16(base + off,            pAh + g);
                cpa16(base + SECT + off,     pAl + g);
                cpa16(base + 2 * SECT + off, pBh + g);
                cpa16(base + 3 * SECT + off, pBl + g);
            }
            {
                uint32_t off = (uint32_t)(r1c * ROWB + c1c * 16);
                size_t g = (size_t)r1c * K2 + kb + (size_t)c1c * 16;
                cpa16(base + off,            pAh + g);
                cpa16(base + SECT + off,     pAl + g);
                cpa16(base + 2 * SECT + off, pBh + g);
                cpa16(base + 3 * SECT + off, pBl + g);
            }
        }
        asm volatile("cp.async.commit_group;" ::: "memory");
    }

    // ---- epilogue (register accumulators -> global) ----
    const size_t mw = m0 + wm * 64;
    const size_t nw = n0 + wn * 32;
    const int tr = lane >> 2;
    const int tc = (lane & 3) * 2;

#pragma unroll
    for (int mi = 0; mi < 4; ++mi) {
#pragma unroll
        for (int ni = 0; ni < 4; ++ni) {
            const float* c = acc[mi][ni];
            const size_t row = mw + mi * 16 + tr;
            const size_t col = nw + ni * 8 + tc;
#pragma unroll
            for (int h = 0; h < 2; ++h) {
                const size_t rr = row + h * 8;
                const size_t base = rr * (size_t)N + col;
                float v0 = c[h * 2], v1 = c[h * 2 + 1];
                if (epi == 0) {
                    v0 = fmaxf(v0, 0.0f); v0 *= v0;
                    v1 = fmaxf(v1, 0.0f); v1 *= v1;
                    __nv_bfloat16 h0, l0, h1, l1;
                    split1(v0, h0, l0);
                    split1(v1, h1, l1);
                    *reinterpret_cast<uint32_t*>(Ch + base) = pbf2(h0, h1);
                    *reinterpret_cast<uint32_t*>(Cl + base) = pbf2(l0, l1);
                } else if (epi == 1) {
                    float2 o;
                    o.x = 1.0f / (1.0f + expf(-v0));
                    o.y = 1.0f / (1.0f + expf(-v1));
                    *reinterpret_cast<float2*>(Cf + base) = o;
                } else {
                    float2 rv = *reinterpret_cast<const float2*>(Rm + base);
                    float2 o;
                    o.x = v0 * rv.x;
                    o.y = v1 * rv.y;
                    *reinterpret_cast<float2*>(Cf + base) = o;
                }
            }
        }
    }
}

// ---------------- launch -----------------------------------------------------
extern "C" void kernel_launch(void* const* d_in, const int* in_sizes, int n_in,
                              void* d_out, int out_size) {
    const float* x  = (const float*)d_in[0];
    const float* ls = (const float*)d_in[1];
    const float* mk = (const float*)d_in[2];
    const float* mr = (const float*)d_in[3];
    const float* kw = (const float*)d_in[4];   // (F, C)
    const float* rw = (const float*)d_in[5];   // (C, C)
    const float* vw = (const float*)d_in[6];   // (C, F)
    float* out = (float*)d_out;

    __nv_bfloat16 *xkh, *xkl, *xrh, *xrl, *sh, *sl, *kwh, *kwl, *rwh, *rwl, *vwh, *vwl;
    float* r;
    cudaGetSymbolAddress((void**)&xkh, g_xkh);
    cudaGetSymbolAddress((void**)&xkl, g_xkl);
    cudaGetSymbolAddress((void**)&xrh, g_xrh);
    cudaGetSymbolAddress((void**)&xrl, g_xrl);
    cudaGetSymbolAddress((void**)&sh,  g_sh);
    cudaGetSymbolAddress((void**)&sl,  g_sl);
    cudaGetSymbolAddress((void**)&kwh, g_kwh);
    cudaGetSymbolAddress((void**)&kwl, g_kwl);
    cudaGetSymbolAddress((void**)&rwh, g_rwh);
    cudaGetSymbolAddress((void**)&rwl, g_rwl);
    cudaGetSymbolAddress((void**)&vwh, g_vwh);
    cudaGetSymbolAddress((void**)&vwl, g_vwl);
    cudaGetSymbolAddress((void**)&r,   g_r);

    cudaFuncSetAttribute(gemm_mma, cudaFuncAttributeMaxDynamicSharedMemorySize, SMEMSZ);

    // 1) token-shift mix + split
    mix_split_kernel<<<(MDIM * (CDIM / 4)) / 256, 256>>>(
        (const float4*)x, (const float4*)ls, (const float4*)mk, (const float4*)mr,
        (uint2*)xkh, (uint2*)xkl, (uint2*)xrh, (uint2*)xrl);

    // 2) weight splits
    {
        size_t n8;
        n8 = (size_t)FDIM * CDIM / 8;
        split_kernel<<<(unsigned)((n8 + 255) / 256), 256>>>((const float4*)kw, (uint4*)kwh, (uint4*)kwl, n8);
        n8 = (size_t)CDIM * CDIM / 8;
        split_kernel<<<(unsigned)((n8 + 255) / 256), 256>>>((const float4*)rw, (uint4*)rwh, (uint4*)rwl, n8);
        n8 = (size_t)CDIM * FDIM / 8;
        split_kernel<<<(unsigned)((n8 + 255) / 256), 256>>>((const float4*)vw, (uint4*)vwh, (uint4*)vwl, n8);
    }

    // 3) S = relu(xk @ Kw^T)^2  -> split bf16       [M=8192, N=14336, K=4096]
    gemm_mma<<<(MDIM / 128) * (FDIM / 128), 256, SMEMSZ>>>(
        xkh, xkl, kwh, kwl, FDIM, CDIM, FDIM / 128, 0, nullptr, sh, sl, nullptr);

    // 4) R = sigmoid(xr @ Rw^T) -> fp32             [M=8192, N=4096, K=4096]
    gemm_mma<<<(MDIM / 128) * (CDIM / 128), 256, SMEMSZ>>>(
        xrh, xrl, rwh, rwl, CDIM, CDIM, CDIM / 128, 1, r, nullptr, nullptr, nullptr);

    // 5) out = R * (S @ Vw^T)   -> fp32             [M=8192, N=4096, K=14336]
    gemm_mma<<<(MDIM / 128) * (CDIM / 128), 256, SMEMSZ>>>(
        sh, sl, vwh, vwl, CDIM, FDIM, CDIM / 128, 2, out, nullptr, nullptr, r);

    // 6) new_state = x[:, -1, :]
    state_kernel<<<(BDIM * CDIM) / 256, 256>>>(x, out + (size_t)MDIM * CDIM);
}

// round 4
// speedup vs baseline: 2.5279x; 1.1038x over previous
#include <cuda_runtime.h>
#include <cuda_bf16.h>
#include <cstdint>
#include <math.h>

#define BDIM 4
#define TDIM 2048
#define CDIM 4096
#define FDIM 14336
#define MDIM (BDIM * TDIM)   // 8192

// ---------------- scratch (device globals; allocation-free rule) -----------
__device__ __nv_bfloat16 g_xkh[(size_t)MDIM * CDIM];
__device__ __nv_bfloat16 g_xkl[(size_t)MDIM * CDIM];
__device__ __nv_bfloat16 g_xrh[(size_t)MDIM * CDIM];
__device__ __nv_bfloat16 g_xrl[(size_t)MDIM * CDIM];
__device__ __nv_bfloat16 g_sh [(size_t)MDIM * FDIM];
__device__ __nv_bfloat16 g_sl [(size_t)MDIM * FDIM];
__device__ __nv_bfloat16 g_kwh[(size_t)FDIM * CDIM];
__device__ __nv_bfloat16 g_kwl[(size_t)FDIM * CDIM];
__device__ __nv_bfloat16 g_rwh[(size_t)CDIM * CDIM];
__device__ __nv_bfloat16 g_rwl[(size_t)CDIM * CDIM];
__device__ __nv_bfloat16 g_vwh[(size_t)CDIM * FDIM];
__device__ __nv_bfloat16 g_vwl[(size_t)CDIM * FDIM];
__device__ float         g_r  [(size_t)MDIM * CDIM];

// ---------------- helpers ----------------------------------------------------
__device__ __forceinline__ uint32_t smem_u32(const void* p) {
    uint32_t a;
    asm("{ .reg .u64 t; cvta.to.shared.u64 t, %1; cvt.u32.u64 %0, t; }" : "=r"(a) : "l"(p));
    return a;
}
__device__ __forceinline__ void cpa16(uint32_t dst, const void* src) {
    asm volatile("cp.async.cg.shared.global [%0], [%1], 16;" :: "r"(dst), "l"(src));
}
__device__ __forceinline__ void ldsm4(uint32_t& r0, uint32_t& r1, uint32_t& r2, uint32_t& r3,
                                      uint32_t addr) {
    asm volatile("ldmatrix.sync.aligned.m8n8.x4.shared.b16 {%0,%1,%2,%3}, [%4];"
                 : "=r"(r0), "=r"(r1), "=r"(r2), "=r"(r3) : "r"(addr));
}
__device__ __forceinline__ void mma_bf16(float* c, const uint32_t* a, const uint32_t* b) {
    asm volatile(
        "mma.sync.aligned.m16n8k16.row.col.f32.bf16.bf16.f32 "
        "{%0,%1,%2,%3}, {%4,%5,%6,%7}, {%8,%9}, {%0,%1,%2,%3};"
        : "+f"(c[0]), "+f"(c[1]), "+f"(c[2]), "+f"(c[3])
        : "r"(a[0]), "r"(a[1]), "r"(a[2]), "r"(a[3]), "r"(b[0]), "r"(b[1]));
}
__device__ __forceinline__ uint32_t pbf2(__nv_bfloat16 a, __nv_bfloat16 b) {
    __nv_bfloat162 t = __halves2bfloat162(a, b);
    return *reinterpret_cast<uint32_t*>(&t);
}
__device__ __forceinline__ void split1(float v, __nv_bfloat16& h, __nv_bfloat16& l) {
    h = __float2bfloat16_rn(v);
    l = __float2bfloat16_rn(v - __bfloat162float(h));
}

// ---------------- elementwise kernels ---------------------------------------
__global__ void mix_split_kernel(const float4* __restrict__ x,
                                 const float4* __restrict__ ls,
                                 const float4* __restrict__ mk,
                                 const float4* __restrict__ mr,
                                 uint2* __restrict__ xkh, uint2* __restrict__ xkl,
                                 uint2* __restrict__ xrh, uint2* __restrict__ xrl) {
    const int C4 = CDIM / 4;
    int idx = blockIdx.x * blockDim.x + threadIdx.x;
    int c4 = idx % C4;
    int bt = idx / C4;
    int t  = bt % TDIM;
    int b  = bt / TDIM;

    float4 xv = x[idx];
    float4 pv = (t == 0) ? ls[b * C4 + c4] : x[idx - C4];
    float4 k4 = mk[c4];
    float4 r4 = mr[c4];

    float kk[4], rr[4];
    kk[0] = fmaf(pv.x - xv.x, k4.x, xv.x);
    kk[1] = fmaf(pv.y - xv.y, k4.y, xv.y);
    kk[2] = fmaf(pv.z - xv.z, k4.z, xv.z);
    kk[3] = fmaf(pv.w - xv.w, k4.w, xv.w);
    rr[0] = fmaf(pv.x - xv.x, r4.x, xv.x);
    rr[1] = fmaf(pv.y - xv.y, r4.y, xv.y);
    rr[2] = fmaf(pv.z - xv.z, r4.z, xv.z);
    rr[3] = fmaf(pv.w - xv.w, r4.w, xv.w);

    __nv_bfloat16 h0, l0, h1, l1, h2, l2, h3, l3;
    split1(kk[0], h0, l0); split1(kk[1], h1, l1);
    split1(kk[2], h2, l2); split1(kk[3], h3, l3);
    xkh[idx] = make_uint2(pbf2(h0, h1), pbf2(h2, h3));
    xkl[idx] = make_uint2(pbf2(l0, l1), pbf2(l2, l3));
    split1(rr[0], h0, l0); split1(rr[1], h1, l1);
    split1(rr[2], h2, l2); split1(rr[3], h3, l3);
    xrh[idx] = make_uint2(pbf2(h0, h1), pbf2(h2, h3));
    xrl[idx] = make_uint2(pbf2(l0, l1), pbf2(l2, l3));
}

__global__ void split_kernel(const float4* __restrict__ in,
                             uint4* __restrict__ oh, uint4* __restrict__ ol,
                             size_t n8) {
    size_t i = (size_t)blockIdx.x * blockDim.x + threadIdx.x;
    if (i >= n8) return;
    float4 a = in[2 * i], b = in[2 * i + 1];
    float v[8] = {a.x, a.y, a.z, a.w, b.x, b.y, b.z, b.w};
    uint32_t hw[4], lw[4];
#pragma unroll
    for (int j = 0; j < 4; ++j) {
        __nv_bfloat16 h0, l0, h1, l1;
        split1(v[2 * j], h0, l0);
        split1(v[2 * j + 1], h1, l1);
        hw[j] = pbf2(h0, h1);
        lw[j] = pbf2(l0, l1);
    }
    oh[i] = make_uint4(hw[0], hw[1], hw[2], hw[3]);
    ol[i] = make_uint4(lw[0], lw[1], lw[2], lw[3]);
}

__global__ void state_kernel(const float* __restrict__ x, float* __restrict__ outs) {
    int idx = blockIdx.x * blockDim.x + threadIdx.x;
    int b = idx / CDIM;
    int c = idx % CDIM;
    outs[idx] = x[((size_t)b * TDIM + (TDIM - 1)) * CDIM + c];
}

// ---------------- HMMA GEMM --------------------------------------------------
// C[M,N] = A[M,K]*B[N,K]^T, split bf16 3-term, mma.sync m16n8k16 bf16.
// CTA 128x256, warp tile 64x64 (8 warps 2x4), BK=32, 3-stage cp.async.
// smem stage: Ah(128x80) | Al | Bh(256x80) | Bl
#define ROWB   80
#define ASEC   (128 * ROWB)          // 10240
#define BSEC   (256 * ROWB)          // 20480
#define STAGEB (2 * ASEC + 2 * BSEC) // 61440
#define NSTAGE 3
#define SMEMSZ (NSTAGE * STAGEB)     // 184320

__global__ void __launch_bounds__(256, 1)
gemm_mma(const __nv_bfloat16* __restrict__ Ah, const __nv_bfloat16* __restrict__ Al,
         const __nv_bfloat16* __restrict__ Bh, const __nv_bfloat16* __restrict__ Bl,
         int N, int K, int Ntiles, int epi,
         float* __restrict__ Cf,
         __nv_bfloat16* __restrict__ Ch, __nv_bfloat16* __restrict__ Cl,
         const float* __restrict__ Rm) {
    extern __shared__ char smem[];
    const uint32_t sb = smem_u32(smem);
    const int tid  = threadIdx.x;
    const int wid  = tid >> 5;
    const int lane = tid & 31;
    const int wm   = wid & 1;        // 2 warp-rows (64 each)
    const int wn   = wid >> 1;       // 4 warp-cols (64 each)

    // band-swizzled tile mapping (bands of 16 M-tiles)
    int bid = blockIdx.x;
    int bandCtas = 16 * Ntiles;
    int band = bid / bandCtas, rmd = bid % bandCtas;
    int nt = rmd >> 4;
    int mt = band * 16 + (rmd & 15);
    const size_t m0 = (size_t)mt * 128;
    const size_t n0 = (size_t)nt * 256;

    const size_t K2 = (size_t)K * 2;  // bytes per row
    const char* pAh = (const char*)(Ah + m0 * (size_t)K);
    const char* pAl = (const char*)(Al + m0 * (size_t)K);
    const char* pBh = (const char*)(Bh + n0 * (size_t)K);
    const char* pBl = (const char*)(Bl + n0 * (size_t)K);

    const int nk = K >> 5;   // BK = 32

    // loader coords: A sections 512 chunks (2 iters/thread), B sections 1024 (4 iters)
    const int cr = tid >> 2;          // base row
    const int cc = tid & 3;           // 16B chunk in row

    // prologue: stages 0, 1
#pragma unroll
    for (int s = 0; s < 2; ++s) {
        const uint32_t base = sb + s * STAGEB;
        const size_t kb = (size_t)s * 64;
#pragma unroll
        for (int it = 0; it < 2; ++it) {       // A: rows cr, cr+64
            int r = cr + it * 64;
            uint32_t off = (uint32_t)(r * ROWB + cc * 16);
            size_t g = (size_t)r * K2 + kb + (size_t)cc * 16;
            cpa16(base + off,        pAh + g);
            cpa16(base + ASEC + off, pAl + g);
        }
#pragma unroll
        for (int it = 0; it < 4; ++it) {       // B: rows cr, cr+64, cr+128, cr+192
            int r = cr + it * 64;
            uint32_t off = (uint32_t)(r * ROWB + cc * 16);
            size_t g = (size_t)r * K2 + kb + (size_t)cc * 16;
            cpa16(base + 2 * ASEC + off,        pBh + g);
            cpa16(base + 2 * ASEC + BSEC + off, pBl + g);
        }
        asm volatile("cp.async.commit_group;" ::: "memory");
    }

    float acc[4][8][4];
#pragma unroll
    for (int i = 0; i < 4; ++i)
#pragma unroll
        for (int j = 0; j < 8; ++j)
#pragma unroll
            for (int q = 0; q < 4; ++q) acc[i][j][q] = 0.0f;

    // ldmatrix lane offsets
    const uint32_t a_lo = (uint32_t)(((lane & 7) + ((lane >> 3) & 1) * 8) * ROWB + (lane >> 4) * 16);
    const uint32_t b_lo = (uint32_t)(((lane & 7) + (lane >> 4) * 8) * ROWB + ((lane >> 3) & 1) * 16);

    for (int kt = 0; kt < nk; ++kt) {
        asm volatile("cp.async.wait_group 1;" ::: "memory");
        __syncthreads();

        const uint32_t sbase = sb + (kt % NSTAGE) * STAGEB;
        const uint32_t aH = sbase;
        const uint32_t aL = sbase + ASEC;
        const uint32_t bH = sbase + 2 * ASEC;
        const uint32_t bL = sbase + 2 * ASEC + BSEC;

#pragma unroll
        for (int kk = 0; kk < 2; ++kk) {
            const uint32_t kbyte = kk * 32;
            uint32_t ah[4][4], al[4][4];
#pragma unroll
            for (int mi = 0; mi < 4; ++mi) {
                uint32_t ra = (uint32_t)((wm * 64 + mi * 16) * ROWB) + kbyte + a_lo;
                ldsm4(ah[mi][0], ah[mi][1], ah[mi][2], ah[mi][3], aH + ra);
                ldsm4(al[mi][0], al[mi][1], al[mi][2], al[mi][3], aL + ra);
            }
#pragma unroll
            for (int nh = 0; nh < 2; ++nh) {
                uint32_t bh[4][2], bl[4][2];
#pragma unroll
                for (int nj = 0; nj < 2; ++nj) {
                    uint32_t rb = (uint32_t)((wn * 64 + nh * 32 + nj * 16) * ROWB) + kbyte + b_lo;
                    uint32_t t0, t1, t2, t3;
                    ldsm4(t0, t1, t2, t3, bH + rb);
                    bh[nj * 2][0] = t0; bh[nj * 2][1] = t1;
                    bh[nj * 2 + 1][0] = t2; bh[nj * 2 + 1][1] = t3;
                    ldsm4(t0, t1, t2, t3, bL + rb);
                    bl[nj * 2][0] = t0; bl[nj * 2][1] = t1;
                    bl[nj * 2 + 1][0] = t2; bl[nj * 2 + 1][1] = t3;
                }
#pragma unroll
                for (int mi = 0; mi < 4; ++mi)
#pragma unroll
                    for (int ni = 0; ni < 4; ++ni) {
                        float* c = acc[mi][nh * 4 + ni];
                        mma_bf16(c, ah[mi], bh[ni]);
                        mma_bf16(c, ah[mi], bl[ni]);
                        mma_bf16(c, al[mi], bh[ni]);
                    }
            }
        }

        // stage kt+2 loads (always commit one group)
        if (kt + 2 < nk) {
            const uint32_t base = sb + ((kt + 2) % NSTAGE) * STAGEB;
            const size_t kb = (size_t)(kt + 2) * 64;
#pragma unroll
            for (int it = 0; it < 2; ++it) {
                int r = cr + it * 64;
                uint32_t off = (uint32_t)(r * ROWB + cc * 16);
                size_t g = (size_t)r * K2 + kb + (size_t)cc * 16;
                cpa16(base + off,        pAh + g);
                cpa16(base + ASEC + off, pAl + g);
            }
#pragma unroll
            for (int it = 0; it < 4; ++it) {
                int r = cr + it * 64;
                uint32_t off = (uint32_t)(r * ROWB + cc * 16);
                size_t g = (size_t)r * K2 + kb + (size_t)cc * 16;
                cpa16(base + 2 * ASEC + off,        pBh + g);
                cpa16(base + 2 * ASEC + BSEC + off, pBl + g);
            }
        }
        asm volatile("cp.async.commit_group;" ::: "memory");
    }

    // ---- epilogue (register accumulators -> global) ----
    const size_t mw = m0 + wm * 64;
    const size_t nw = n0 + wn * 64;
    const int tr = lane >> 2;
    const int tc = (lane & 3) * 2;

#pragma unroll
    for (int mi = 0; mi < 4; ++mi) {
#pragma unroll
        for (int nj = 0; nj < 8; ++nj) {
            const float* c = acc[mi][nj];
            const size_t row = mw + mi * 16 + tr;
            const size_t col = nw + nj * 8 + tc;
#pragma unroll
            for (int h = 0; h < 2; ++h) {
                const size_t rr = row + h * 8;
                const size_t base = rr * (size_t)N + col;
                float v0 = c[h * 2], v1 = c[h * 2 + 1];
                if (epi == 0) {
                    v0 = fmaxf(v0, 0.0f); v0 *= v0;
                    v1 = fmaxf(v1, 0.0f); v1 *= v1;
                    __nv_bfloat16 h0, l0, h1, l1;
                    split1(v0, h0, l0);
                    split1(v1, h1, l1);
                    *reinterpret_cast<uint32_t*>(Ch + base) = pbf2(h0, h1);
                    *reinterpret_cast<uint32_t*>(Cl + base) = pbf2(l0, l1);
                } else if (epi == 1) {
                    float2 o;
                    o.x = 1.0f / (1.0f + expf(-v0));
                    o.y = 1.0f / (1.0f + expf(-v1));
                    *reinterpret_cast<float2*>(Cf + base) = o;
                } else {
                    float2 rv = *reinterpret_cast<const float2*>(Rm + base);
                    float2 o;
                    o.x = v0 * rv.x;
                    o.y = v1 * rv.y;
                    *reinterpret_cast<float2*>(Cf + base) = o;
                }
            }
        }
    }
}

// ---------------- launch -----------------------------------------------------
extern "C" void kernel_launch(void* const* d_in, const int* in_sizes, int n_in,
                              void* d_out, int out_size) {
    const float* x  = (const float*)d_in[0];
    const float* ls = (const float*)d_in[1];
    const float* mk = (const float*)d_in[2];
    const float* mr = (const float*)d_in[3];
    const float* kw = (const float*)d_in[4];   // (F, C)
    const float* rw = (const float*)d_in[5];   // (C, C)
    const float* vw = (const float*)d_in[6];   // (C, F)
    float* out = (float*)d_out;

    __nv_bfloat16 *xkh, *xkl, *xrh, *xrl, *sh, *sl, *kwh, *kwl, *rwh, *rwl, *vwh, *vwl;
    float* r;
    cudaGetSymbolAddress((void**)&xkh, g_xkh);
    cudaGetSymbolAddress((void**)&xkl, g_xkl);
    cudaGetSymbolAddress((void**)&xrh, g_xrh);
    cudaGetSymbolAddress((void**)&xrl, g_xrl);
    cudaGetSymbolAddress((void**)&sh,  g_sh);
    cudaGetSymbolAddress((void**)&sl,  g_sl);
    cudaGetSymbolAddress((void**)&kwh, g_kwh);
    cudaGetSymbolAddress((void**)&kwl, g_kwl);
    cudaGetSymbolAddress((void**)&rwh, g_rwh);
    cudaGetSymbolAddress((void**)&rwl, g_rwl);
    cudaGetSymbolAddress((void**)&vwh, g_vwh);
    cudaGetSymbolAddress((void**)&vwl, g_vwl);
    cudaGetSymbolAddress((void**)&r,   g_r);

    cudaFuncSetAttribute(gemm_mma, cudaFuncAttributeMaxDynamicSharedMemorySize, SMEMSZ);

    // 1) token-shift mix + split
    mix_split_kernel<<<(MDIM * (CDIM / 4)) / 256, 256>>>(
        (const float4*)x, (const float4*)ls, (const float4*)mk, (const float4*)mr,
        (uint2*)xkh, (uint2*)xkl, (uint2*)xrh, (uint2*)xrl);

    // 2) weight splits
    {
        size_t n8;
        n8 = (size_t)FDIM * CDIM / 8;
        split_kernel<<<(unsigned)((n8 + 255) / 256), 256>>>((const float4*)kw, (uint4*)kwh, (uint4*)kwl, n8);
        n8 = (size_t)CDIM * CDIM / 8;
        split_kernel<<<(unsigned)((n8 + 255) / 256), 256>>>((const float4*)rw, (uint4*)rwh, (uint4*)rwl, n8);
        n8 = (size_t)CDIM * FDIM / 8;
        split_kernel<<<(unsigned)((n8 + 255) / 256), 256>>>((const float4*)vw, (uint4*)vwh, (uint4*)vwl, n8);
    }

    // 3) S = relu(xk @ Kw^T)^2  -> split bf16       [M=8192, N=14336, K=4096]
    gemm_mma<<<(MDIM / 128) * (FDIM / 256), 256, SMEMSZ>>>(
        xkh, xkl, kwh, kwl, FDIM, CDIM, FDIM / 256, 0, nullptr, sh, sl, nullptr);

    // 4) R = sigmoid(xr @ Rw^T) -> fp32             [M=8192, N=4096, K=4096]
    gemm_mma<<<(MDIM / 128) * (CDIM / 256), 256, SMEMSZ>>>(
        xrh, xrl, rwh, rwl, CDIM, CDIM, CDIM / 256, 1, r, nullptr, nullptr, nullptr);

    // 5) out = R * (S @ Vw^T)   -> fp32             [M=8192, N=4096, K=14336]
    gemm_mma<<<(MDIM / 128) * (CDIM / 256), 256, SMEMSZ>>>(
        sh, sl, vwh, vwl, CDIM, FDIM, CDIM / 256, 2, out, nullptr, nullptr, r);

    // 6) new_state = x[:, -1, :]
    state_kernel<<<(BDIM * CDIM) / 256, 256>>>(x, out + (size_t)MDIM * CDIM);
}

// round 5
// speedup vs baseline: 2.7638x; 1.0934x over previous
#include <cuda_runtime.h>
#include <cuda_bf16.h>
#include <cstdint>
#include <math.h>

#define BDIM 4
#define TDIM 2048
#define CDIM 4096
#define FDIM 14336
#define MDIM (BDIM * TDIM)   // 8192

// ---------------- scratch (device globals; allocation-free rule) -----------
__device__ __nv_bfloat16 g_xkh[(size_t)MDIM * CDIM];
__device__ __nv_bfloat16 g_xkl[(size_t)MDIM * CDIM];
__device__ __nv_bfloat16 g_xrh[(size_t)MDIM * CDIM];
__device__ __nv_bfloat16 g_xrl[(size_t)MDIM * CDIM];
__device__ __nv_bfloat16 g_sh [(size_t)MDIM * FDIM];
__device__ __nv_bfloat16 g_sl [(size_t)MDIM * FDIM];
__device__ __nv_bfloat16 g_kwh[(size_t)FDIM * CDIM];
__device__ __nv_bfloat16 g_kwl[(size_t)FDIM * CDIM];
__device__ __nv_bfloat16 g_rwh[(size_t)CDIM * CDIM];
__device__ __nv_bfloat16 g_rwl[(size_t)CDIM * CDIM];
__device__ __nv_bfloat16 g_vwh[(size_t)CDIM * FDIM];
__device__ __nv_bfloat16 g_vwl[(size_t)CDIM * FDIM];
__device__ float         g_r  [(size_t)MDIM * CDIM];

// ---------------- helpers ----------------------------------------------------
__device__ __forceinline__ uint32_t smem_u32(const void* p) {
    uint32_t a;
    asm("{ .reg .u64 t; cvta.to.shared.u64 t, %1; cvt.u32.u64 %0, t; }" : "=r"(a) : "l"(p));
    return a;
}
__device__ __forceinline__ void cpa16(uint32_t dst, const void* src) {
    asm volatile("cp.async.cg.shared.global [%0], [%1], 16;" :: "r"(dst), "l"(src));
}
__device__ __forceinline__ void ldsm4(uint32_t& r0, uint32_t& r1, uint32_t& r2, uint32_t& r3,
                                      uint32_t addr) {
    asm volatile("ldmatrix.sync.aligned.m8n8.x4.shared.b16 {%0,%1,%2,%3}, [%4];"
                 : "=r"(r0), "=r"(r1), "=r"(r2), "=r"(r3) : "r"(addr));
}
__device__ __forceinline__ void mma_bf16(float* c, const uint32_t* a, const uint32_t* b) {
    asm volatile(
        "mma.sync.aligned.m16n8k16.row.col.f32.bf16.bf16.f32 "
        "{%0,%1,%2,%3}, {%4,%5,%6,%7}, {%8,%9}, {%0,%1,%2,%3};"
        : "+f"(c[0]), "+f"(c[1]), "+f"(c[2]), "+f"(c[3])
        : "r"(a[0]), "r"(a[1]), "r"(a[2]), "r"(a[3]), "r"(b[0]), "r"(b[1]));
}
__device__ __forceinline__ uint32_t pbf2(__nv_bfloat16 a, __nv_bfloat16 b) {
    __nv_bfloat162 t = __halves2bfloat162(a, b);
    return *reinterpret_cast<uint32_t*>(&t);
}
__device__ __forceinline__ void split1(float v, __nv_bfloat16& h, __nv_bfloat16& l) {
    h = __float2bfloat16_rn(v);
    l = __float2bfloat16_rn(v - __bfloat162float(h));
}

// ---------------- elementwise kernels ---------------------------------------
__global__ void mix_split_kernel(const float4* __restrict__ x,
                                 const float4* __restrict__ ls,
                                 const float4* __restrict__ mk,
                                 const float4* __restrict__ mr,
                                 uint2* __restrict__ xkh, uint2* __restrict__ xkl,
                                 uint2* __restrict__ xrh, uint2* __restrict__ xrl) {
    const int C4 = CDIM / 4;
    int idx = blockIdx.x * blockDim.x + threadIdx.x;
    int c4 = idx % C4;
    int bt = idx / C4;
    int t  = bt % TDIM;
    int b  = bt / TDIM;

    float4 xv = x[idx];
    float4 pv = (t == 0) ? ls[b * C4 + c4] : x[idx - C4];
    float4 k4 = mk[c4];
    float4 r4 = mr[c4];

    float kk[4], rr[4];
    kk[0] = fmaf(pv.x - xv.x, k4.x, xv.x);
    kk[1] = fmaf(pv.y - xv.y, k4.y, xv.y);
    kk[2] = fmaf(pv.z - xv.z, k4.z, xv.z);
    kk[3] = fmaf(pv.w - xv.w, k4.w, xv.w);
    rr[0] = fmaf(pv.x - xv.x, r4.x, xv.x);
    rr[1] = fmaf(pv.y - xv.y, r4.y, xv.y);
    rr[2] = fmaf(pv.z - xv.z, r4.z, xv.z);
    rr[3] = fmaf(pv.w - xv.w, r4.w, xv.w);

    __nv_bfloat16 h0, l0, h1, l1, h2, l2, h3, l3;
    split1(kk[0], h0, l0); split1(kk[1], h1, l1);
    split1(kk[2], h2, l2); split1(kk[3], h3, l3);
    xkh[idx] = make_uint2(pbf2(h0, h1), pbf2(h2, h3));
    xkl[idx] = make_uint2(pbf2(l0, l1), pbf2(l2, l3));
    split1(rr[0], h0, l0); split1(rr[1], h1, l1);
    split1(rr[2], h2, l2); split1(rr[3], h3, l3);
    xrh[idx] = make_uint2(pbf2(h0, h1), pbf2(h2, h3));
    xrl[idx] = make_uint2(pbf2(l0, l1), pbf2(l2, l3));
}

__global__ void split_kernel(const float4* __restrict__ in,
                             uint4* __restrict__ oh, uint4* __restrict__ ol,
                             size_t n8) {
    size_t i = (size_t)blockIdx.x * blockDim.x + threadIdx.x;
    if (i >= n8) return;
    float4 a = in[2 * i], b = in[2 * i + 1];
    float v[8] = {a.x, a.y, a.z, a.w, b.x, b.y, b.z, b.w};
    uint32_t hw[4], lw[4];
#pragma unroll
    for (int j = 0; j < 4; ++j) {
        __nv_bfloat16 h0, l0, h1, l1;
        split1(v[2 * j], h0, l0);
        split1(v[2 * j + 1], h1, l1);
        hw[j] = pbf2(h0, h1);
        lw[j] = pbf2(l0, l1);
    }
    oh[i] = make_uint4(hw[0], hw[1], hw[2], hw[3]);
    ol[i] = make_uint4(lw[0], lw[1], lw[2], lw[3]);
}

__global__ void state_kernel(const float* __restrict__ x, float* __restrict__ outs) {
    int idx = blockIdx.x * blockDim.x + threadIdx.x;
    int b = idx / CDIM;
    int c = idx % CDIM;
    outs[idx] = x[((size_t)b * TDIM + (TDIM - 1)) * CDIM + c];
}

// ---------------- HMMA GEMM --------------------------------------------------
// C[M,N] = A[M,K]*B[N,K]^T, split bf16 3-term, mma.sync m16n8k16 bf16.
// CTA 128x256, 16 warps (512 threads), warp tile 64x32 (2x8), BK=32,
// 3-stage cp.async. smem stage: Ah(128x80) | Al | Bh(256x80) | Bl
#define ROWB   80
#define ASEC   (128 * ROWB)          // 10240
#define BSEC   (256 * ROWB)          // 20480
#define STAGEB (2 * ASEC + 2 * BSEC) // 61440
#define NSTAGE 3
#define SMEMSZ (NSTAGE * STAGEB)     // 184320

__global__ void __launch_bounds__(512, 1)
gemm_mma(const __nv_bfloat16* __restrict__ Ah, const __nv_bfloat16* __restrict__ Al,
         const __nv_bfloat16* __restrict__ Bh, const __nv_bfloat16* __restrict__ Bl,
         int N, int K, int Ntiles, int epi,
         float* __restrict__ Cf,
         __nv_bfloat16* __restrict__ Ch, __nv_bfloat16* __restrict__ Cl,
         const float* __restrict__ Rm) {
    extern __shared__ char smem[];
    const uint32_t sb = smem_u32(smem);
    const int tid  = threadIdx.x;
    const int wid  = tid >> 5;
    const int lane = tid & 31;
    const int wm   = wid & 1;        // 2 warp-rows (64 each)
    const int wn   = wid >> 1;       // 8 warp-cols (32 each)

    // band-swizzled tile mapping (bands of 16 M-tiles)
    int bid = blockIdx.x;
    int bandCtas = 16 * Ntiles;
    int band = bid / bandCtas, rmd = bid % bandCtas;
    int nt = rmd >> 4;
    int mt = band * 16 + (rmd & 15);
    const size_t m0 = (size_t)mt * 128;
    const size_t n0 = (size_t)nt * 256;

    const size_t K2 = (size_t)K * 2;  // bytes per row
    const char* pAh = (const char*)(Ah + m0 * (size_t)K);
    const char* pAl = (const char*)(Al + m0 * (size_t)K);
    const char* pBh = (const char*)(Bh + n0 * (size_t)K);
    const char* pBl = (const char*)(Bl + n0 * (size_t)K);

    const int nk = K >> 5;   // BK = 32

    // loader coords (512 threads): A 512 chunks (1/thread), B 1024 (2/thread)
    const int cr = tid >> 2;          // row 0..127
    const int cc = tid & 3;           // 16B chunk in row

    // prologue: stages 0, 1
#pragma unroll
    for (int s = 0; s < 2; ++s) {
        const uint32_t base = sb + s * STAGEB;
        const size_t kb = (size_t)s * 64;
        {
            uint32_t off = (uint32_t)(cr * ROWB + cc * 16);
            size_t g = (size_t)cr * K2 + kb + (size_t)cc * 16;
            cpa16(base + off,        pAh + g);
            cpa16(base + ASEC + off, pAl + g);
        }
#pragma unroll
        for (int it = 0; it < 2; ++it) {       // B rows cr, cr+128
            int r = cr + it * 128;
            uint32_t off = (uint32_t)(r * ROWB + cc * 16);
            size_t g = (size_t)r * K2 + kb + (size_t)cc * 16;
            cpa16(base + 2 * ASEC + off,        pBh + g);
            cpa16(base + 2 * ASEC + BSEC + off, pBl + g);
        }
        asm volatile("cp.async.commit_group;" ::: "memory");
    }

    float acc[4][4][4];
#pragma unroll
    for (int i = 0; i < 4; ++i)
#pragma unroll
        for (int j = 0; j < 4; ++j)
#pragma unroll
            for (int q = 0; q < 4; ++q) acc[i][j][q] = 0.0f;

    // ldmatrix lane offsets
    const uint32_t a_lo = (uint32_t)(((lane & 7) + ((lane >> 3) & 1) * 8) * ROWB + (lane >> 4) * 16);
    const uint32_t b_lo = (uint32_t)(((lane & 7) + (lane >> 4) * 8) * ROWB + ((lane >> 3) & 1) * 16);

    for (int kt = 0; kt < nk; ++kt) {
        asm volatile("cp.async.wait_group 1;" ::: "memory");
        __syncthreads();

        const uint32_t sbase = sb + (kt % NSTAGE) * STAGEB;
        const uint32_t aH = sbase;
        const uint32_t aL = sbase + ASEC;
        const uint32_t bH = sbase + 2 * ASEC;
        const uint32_t bL = sbase + 2 * ASEC + BSEC;

#pragma unroll
        for (int kk = 0; kk < 2; ++kk) {
            const uint32_t kbyte = kk * 32;
            uint32_t ah[4][4], al[4][4], bh[4][2], bl[4][2];
#pragma unroll
            for (int mi = 0; mi < 4; ++mi) {
                uint32_t ra = (uint32_t)((wm * 64 + mi * 16) * ROWB) + kbyte + a_lo;
                ldsm4(ah[mi][0], ah[mi][1], ah[mi][2], ah[mi][3], aH + ra);
                ldsm4(al[mi][0], al[mi][1], al[mi][2], al[mi][3], aL + ra);
            }
#pragma unroll
            for (int nj = 0; nj < 2; ++nj) {
                uint32_t rb = (uint32_t)((wn * 32 + nj * 16) * ROWB) + kbyte + b_lo;
                uint32_t t0, t1, t2, t3;
                ldsm4(t0, t1, t2, t3, bH + rb);
                bh[nj * 2][0] = t0; bh[nj * 2][1] = t1;
                bh[nj * 2 + 1][0] = t2; bh[nj * 2 + 1][1] = t3;
                ldsm4(t0, t1, t2, t3, bL + rb);
                bl[nj * 2][0] = t0; bl[nj * 2][1] = t1;
                bl[nj * 2 + 1][0] = t2; bl[nj * 2 + 1][1] = t3;
            }
#pragma unroll
            for (int mi = 0; mi < 4; ++mi)
#pragma unroll
                for (int ni = 0; ni < 4; ++ni) {
                    float* c = acc[mi][ni];
                    mma_bf16(c, ah[mi], bh[ni]);
                    mma_bf16(c, ah[mi], bl[ni]);
                    mma_bf16(c, al[mi], bh[ni]);
                }
        }

        // stage kt+2 loads (always commit one group)
        if (kt + 2 < nk) {
            const uint32_t base = sb + ((kt + 2) % NSTAGE) * STAGEB;
            const size_t kb = (size_t)(kt + 2) * 64;
            {
                uint32_t off = (uint32_t)(cr * ROWB + cc * 16);
                size_t g = (size_t)cr * K2 + kb + (size_t)cc * 16;
                cpa16(base + off,        pAh + g);
                cpa16(base + ASEC + off, pAl + g);
            }
#pragma unroll
            for (int it = 0; it < 2; ++it) {
                int r = cr + it * 128;
                uint32_t off = (uint32_t)(r * ROWB + cc * 16);
                size_t g = (size_t)r * K2 + kb + (size_t)cc * 16;
                cpa16(base + 2 * ASEC + off,        pBh + g);
                cpa16(base + 2 * ASEC + BSEC + off, pBl + g);
            }
        }
        asm volatile("cp.async.commit_group;" ::: "memory");
    }

    // ---- epilogue (register accumulators -> global) ----
    const size_t mw = m0 + wm * 64;
    const size_t nw = n0 + wn * 32;
    const int tr = lane >> 2;
    const int tc = (lane & 3) * 2;

#pragma unroll
    for (int mi = 0; mi < 4; ++mi) {
#pragma unroll
        for (int nj = 0; nj < 4; ++nj) {
            const float* c = acc[mi][nj];
            const size_t row = mw + mi * 16 + tr;
            const size_t col = nw + nj * 8 + tc;
#pragma unroll
            for (int h = 0; h < 2; ++h) {
                const size_t rr = row + h * 8;
                const size_t base = rr * (size_t)N + col;
                float v0 = c[h * 2], v1 = c[h * 2 + 1];
                if (epi == 0) {
                    v0 = fmaxf(v0, 0.0f); v0 *= v0;
                    v1 = fmaxf(v1, 0.0f); v1 *= v1;
                    __nv_bfloat16 h0, l0, h1, l1;
                    split1(v0, h0, l0);
                    split1(v1, h1, l1);
                    *reinterpret_cast<uint32_t*>(Ch + base) = pbf2(h0, h1);
                    *reinterpret_cast<uint32_t*>(Cl + base) = pbf2(l0, l1);
                } else if (epi == 1) {
                    float2 o;
                    o.x = 1.0f / (1.0f + expf(-v0));
                    o.y = 1.0f / (1.0f + expf(-v1));
                    *reinterpret_cast<float2*>(Cf + base) = o;
                } else {
                    float2 rv = *reinterpret_cast<const float2*>(Rm + base);
                    float2 o;
                    o.x = v0 * rv.x;
                    o.y = v1 * rv.y;
                    *reinterpret_cast<float2*>(Cf + base) = o;
                }
            }
        }
    }
}

// ---------------- launch -----------------------------------------------------
extern "C" void kernel_launch(void* const* d_in, const int* in_sizes, int n_in,
                              void* d_out, int out_size) {
    const float* x  = (const float*)d_in[0];
    const float* ls = (const float*)d_in[1];
    const float* mk = (const float*)d_in[2];
    const float* mr = (const float*)d_in[3];
    const float* kw = (const float*)d_in[4];   // (F, C)
    const float* rw = (const float*)d_in[5];   // (C, C)
    const float* vw = (const float*)d_in[6];   // (C, F)
    float* out = (float*)d_out;

    __nv_bfloat16 *xkh, *xkl, *xrh, *xrl, *sh, *sl, *kwh, *kwl, *rwh, *rwl, *vwh, *vwl;
    float* r;
    cudaGetSymbolAddress((void**)&xkh, g_xkh);
    cudaGetSymbolAddress((void**)&xkl, g_xkl);
    cudaGetSymbolAddress((void**)&xrh, g_xrh);
    cudaGetSymbolAddress((void**)&xrl, g_xrl);
    cudaGetSymbolAddress((void**)&sh,  g_sh);
    cudaGetSymbolAddress((void**)&sl,  g_sl);
    cudaGetSymbolAddress((void**)&kwh, g_kwh);
    cudaGetSymbolAddress((void**)&kwl, g_kwl);
    cudaGetSymbolAddress((void**)&rwh, g_rwh);
    cudaGetSymbolAddress((void**)&rwl, g_rwl);
    cudaGetSymbolAddress((void**)&vwh, g_vwh);
    cudaGetSymbolAddress((void**)&vwl, g_vwl);
    cudaGetSymbolAddress((void**)&r,   g_r);

    cudaFuncSetAttribute(gemm_mma, cudaFuncAttributeMaxDynamicSharedMemorySize, SMEMSZ);

    // 1) token-shift mix + split
    mix_split_kernel<<<(MDIM * (CDIM / 4)) / 256, 256>>>(
        (const float4*)x, (const float4*)ls, (const float4*)mk, (const float4*)mr,
        (uint2*)xkh, (uint2*)xkl, (uint2*)xrh, (uint2*)xrl);

    // 2) weight splits
    {
        size_t n8;
        n8 = (size_t)FDIM * CDIM / 8;
        split_kernel<<<(unsigned)((n8 + 255) / 256), 256>>>((const float4*)kw, (uint4*)kwh, (uint4*)kwl, n8);
        n8 = (size_t)CDIM * CDIM / 8;
        split_kernel<<<(unsigned)((n8 + 255) / 256), 256>>>((const float4*)rw, (uint4*)rwh, (uint4*)rwl, n8);
        n8 = (size_t)CDIM * FDIM / 8;
        split_kernel<<<(unsigned)((n8 + 255) / 256), 256>>>((const float4*)vw, (uint4*)vwh, (uint4*)vwl, n8);
    }

    // 3) S = relu(xk @ Kw^T)^2  -> split bf16       [M=8192, N=14336, K=4096]
    gemm_mma<<<(MDIM / 128) * (FDIM / 256), 512, SMEMSZ>>>(
        xkh, xkl, kwh, kwl, FDIM, CDIM, FDIM / 256, 0, nullptr, sh, sl, nullptr);

    // 4) R = sigmoid(xr @ Rw^T) -> fp32             [M=8192, N=4096, K=4096]
    gemm_mma<<<(MDIM / 128) * (CDIM / 256), 512, SMEMSZ>>>(
        xrh, xrl, rwh, rwl, CDIM, CDIM, CDIM / 256, 1, r, nullptr, nullptr, nullptr);

    // 5) out = R * (S @ Vw^T)   -> fp32             [M=8192, N=4096, K=14336]
    gemm_mma<<<(MDIM / 128) * (CDIM / 256), 512, SMEMSZ>>>(
        sh, sl, vwh, vwl, CDIM, FDIM, CDIM / 256, 2, out, nullptr, nullptr, r);

    // 6) new_state = x[:, -1, :]
    state_kernel<<<(BDIM * CDIM) / 256, 256>>>(x, out + (size_t)MDIM * CDIM);
}